// round 9
// baseline (speedup 1.0000x reference)
#include <cuda_runtime.h>
#include <cstdint>

#define SEQ    2048
#define DIMM   4096
#define NHEADS 32
#define NKVH   8
#define HD     128
#define QD     (NHEADS * HD)   // 4096
#define KVD    (NKVH * HD)     // 1024

// Scratch (no cudaMalloc allowed)
__device__ float g_q[SEQ * QD];
__device__ float g_k[SEQ * KVD];
__device__ float g_v[SEQ * KVD];
__device__ float g_att[SEQ * QD];

__device__ __forceinline__ uint32_t f2tf32(float x) {
    uint32_t r;
    asm("cvt.rna.tf32.f32 %0, %1;" : "=r"(r) : "f"(x));
    return r;
}

__device__ __forceinline__ void mma_tf32(float* c, const uint32_t* a, const uint32_t* b) {
    asm volatile(
        "mma.sync.aligned.m16n8k8.row.col.f32.tf32.tf32.f32 "
        "{%0,%1,%2,%3}, {%4,%5,%6,%7}, {%8,%9}, {%0,%1,%2,%3};\n"
        : "+f"(c[0]), "+f"(c[1]), "+f"(c[2]), "+f"(c[3])
        : "r"(a[0]), "r"(a[1]), "r"(a[2]), "r"(a[3]),
          "r"(b[0]), "r"(b[1]));
}

__device__ __forceinline__ void cp_async16(void* smem_dst, const void* gmem_src) {
    uint32_t dst = (uint32_t)__cvta_generic_to_shared(smem_dst);
    asm volatile("cp.async.cg.shared.global [%0], [%1], 16;\n"
                 :: "r"(dst), "l"(gmem_src));
}
__device__ __forceinline__ void cp_commit() {
    asm volatile("cp.async.commit_group;\n");
}
__device__ __forceinline__ void cp_wait1() {
    asm volatile("cp.async.wait_group 1;\n");
}

// ===========================================================================
// TF32 tensor-core GEMM — 4-stage cp.async ring (unchanged from R7)
// ===========================================================================
#define BM 128
#define BN 128
#define BK 32
#define ASTRIDE 36
#define BSTRIDE 136
#define STAGE_FLOATS (BM * ASTRIDE + BK * BSTRIDE)   // 8960
#define NSTAGE 4
#define GEMM_SMEM_BYTES (NSTAGE * STAGE_FLOATS * 4)  // 143360

__global__ __launch_bounds__(256, 1) void gemm_tf32(
    const float* __restrict__ A, const float* __restrict__ B,
    float* __restrict__ C, int M, int N, int K)
{
    extern __shared__ float sm[];

    const int tid = threadIdx.x;
    const int bx = blockIdx.x, by = blockIdx.y;

    const int arow0 = tid >> 3;
    const int acol4 = (tid & 7) << 2;
    const int brow0 = tid >> 5;
    const int bcol4 = (tid & 31) << 2;

    const int lane = tid & 31;
    const int warp = tid >> 5;
    const int wr = warp >> 2;
    const int wc = warp & 3;
    const int g  = lane >> 2;
    const int tg = lane & 3;
    const int morg = wr * 64;
    const int norg = wc * 32;

    const float* Ab = A + (size_t)by * BM * K;
    const float* Bb = B + (size_t)bx * BN;

    float acc[4][4][4];
#pragma unroll
    for (int mi = 0; mi < 4; mi++)
#pragma unroll
        for (int ni = 0; ni < 4; ni++)
#pragma unroll
            for (int r = 0; r < 4; r++) acc[mi][ni][r] = 0.f;

    const int nk = K / BK;

    auto load_stage = [&](int s, int k0) {
        float* As_ = sm + s * STAGE_FLOATS;
        float* Bs_ = As_ + BM * ASTRIDE;
#pragma unroll
        for (int r = 0; r < BM; r += 32)
            cp_async16(&As_[(arow0 + r) * ASTRIDE + acol4],
                       Ab + (size_t)(arow0 + r) * K + k0 + acol4);
#pragma unroll
        for (int r = 0; r < BK; r += 8)
            cp_async16(&Bs_[(brow0 + r) * BSTRIDE + bcol4],
                       Bb + (size_t)(k0 + brow0 + r) * N + bcol4);
        cp_commit();
    };

    load_stage(0, 0);
    load_stage(1, BK);
    load_stage(2, 2 * BK);

    for (int kt = 0; kt < nk; kt++) {
        asm volatile("cp.async.wait_group 2;\n");
        __syncthreads();
        if (kt + 3 < nk) load_stage((kt + 3) & (NSTAGE - 1), (kt + 3) * BK);
        else             cp_commit();

        const float* As_ = sm + (kt & (NSTAGE - 1)) * STAGE_FLOATS;
        const float* Bs_ = As_ + BM * ASTRIDE;

#pragma unroll
        for (int k8 = 0; k8 < BK; k8 += 8) {
            uint32_t af[4][4], bf[4][2];
#pragma unroll
            for (int mi = 0; mi < 4; mi++) {
                const int r = morg + mi * 16 + g;
                af[mi][0] = f2tf32(As_[(r)     * ASTRIDE + k8 + tg]);
                af[mi][1] = f2tf32(As_[(r + 8) * ASTRIDE + k8 + tg]);
                af[mi][2] = f2tf32(As_[(r)     * ASTRIDE + k8 + tg + 4]);
                af[mi][3] = f2tf32(As_[(r + 8) * ASTRIDE + k8 + tg + 4]);
            }
#pragma unroll
            for (int ni = 0; ni < 4; ni++) {
                const int c = norg + ni * 8 + g;
                bf[ni][0] = f2tf32(Bs_[(k8 + tg)     * BSTRIDE + c]);
                bf[ni][1] = f2tf32(Bs_[(k8 + tg + 4) * BSTRIDE + c]);
            }
#pragma unroll
            for (int mi = 0; mi < 4; mi++)
#pragma unroll
                for (int ni = 0; ni < 4; ni++)
                    mma_tf32(acc[mi][ni], af[mi], bf[ni]);
        }
    }

    float* Cb = C + (size_t)(by * BM) * N + bx * BN;
#pragma unroll
    for (int mi = 0; mi < 4; mi++) {
#pragma unroll
        for (int ni = 0; ni < 4; ni++) {
            const int r0 = morg + mi * 16 + g;
            const int c0 = norg + ni * 8 + tg * 2;
            *(float2*)(&Cb[(size_t)r0 * N + c0]) =
                make_float2(acc[mi][ni][0], acc[mi][ni][1]);
            *(float2*)(&Cb[(size_t)(r0 + 8) * N + c0]) =
                make_float2(acc[mi][ni][2], acc[mi][ni][3]);
        }
    }
}

// ---------------------------------------------------------------------------
// RoPE (interleaved pairs)
// ---------------------------------------------------------------------------
__global__ void rope_kernel(float* __restrict__ t,
                            const float* __restrict__ fc,
                            const float* __restrict__ fs,
                            int nheads, int total)
{
    int idx = blockIdx.x * blockDim.x + threadIdx.x;
    if (idx >= total) return;
    int p = idx & 63;
    int h = (idx >> 6) % nheads;
    int s = idx / (64 * nheads);
    float c  = fc[s * 64 + p];
    float sn = fs[s * 64 + p];
    float* base = t + (size_t)s * nheads * HD + h * HD + 2 * p;
    float re = base[0], im = base[1];
    base[0] = re * c - im * sn;
    base[1] = re * sn + im * c;
}

// ===========================================================================
// Tensor-core flash attention v2 (causal, GQA 4:1).
// 128-row Q tile, 64-col K/V tiles. 512 threads (16 warps), 1 CTA/SM.
// Separate K and V buffers; cp.async pipelining with uniform wait_group 1
// (one tile-load always in flight). Exact bitmask hi/lo V split for PV.
// ===========================================================================
#define QROWS 128
#define KCOLS 64
#define AQSTR 132     // Q & K row stride (4 mod 32)
#define AVSTR 136     // V row stride (8 mod 32)
#define ASSTR 68      // S row stride (4 mod 32)
#define FA2_Q_FLOATS (QROWS * AQSTR)          // 16896
#define FA2_K_FLOATS (KCOLS * AQSTR)          // 8448
#define FA2_V_FLOATS (KCOLS * AVSTR)          // 8704
#define FA2_S_FLOATS (QROWS * ASSTR)          // 8704
#define FA2_SMEM_FLOATS (FA2_Q_FLOATS + FA2_K_FLOATS + FA2_V_FLOATS + FA2_S_FLOATS + 3 * QROWS)
#define FA2_SMEM_BYTES (FA2_SMEM_FLOATS * 4)  // 172544

__global__ __launch_bounds__(512, 1) void flash_attn_tc2(
    const float* __restrict__ Q, const float* __restrict__ K,
    const float* __restrict__ V, float* __restrict__ O)
{
    extern __shared__ float sm[];
    float* Qt   = sm;                              // [128][AQSTR]
    float* Ks   = Qt + FA2_Q_FLOATS;               // [64][AQSTR]
    float* Vs   = Ks + FA2_K_FLOATS;               // [64][AVSTR]
    float* Ss   = Vs + FA2_V_FLOATS;               // [128][ASSTR]
    float* mrow = Ss + FA2_S_FLOATS;               // [128]
    float* lrow = mrow + QROWS;
    float* arow = lrow + QROWS;

    const int tid  = threadIdx.x;
    const int qb   = (int)gridDim.x - 1 - (int)blockIdx.x;  // big tiles first
    const int h    = blockIdx.y, kvh = h >> 2;
    const int lane = tid & 31;
    const int warp = tid >> 5;
    const int g    = lane >> 2;
    const int tg   = lane & 3;
    const int mi   = warp & 7;        // 0..7  (16-row slice of 128)
    const int nj   = warp >> 3;       // 0..1
    const int lr   = tid >> 5;        // 0..15 (loader row)
    const int ld4  = (tid & 31) << 2; // loader col (float4)
    const float scale = 0.08838834764831845f;   // 1/sqrt(128)

    const int mrow0 = mi * 16 + g;

    // softmax: 4 threads per row (128 rows x 4 = 512)
    const int sr = tid >> 2;
    const int sq = (tid & 3) << 4;

    // ---- load Q tile (prescaled), 128 rows ----
#pragma unroll
    for (int rr = 0; rr < QROWS; rr += 16) {
        float4 v = *(const float4*)(Q + (size_t)(qb * QROWS + lr + rr) * QD + h * HD + ld4);
        v.x *= scale; v.y *= scale; v.z *= scale; v.w *= scale;
        *(float4*)(Qt + (lr + rr) * AQSTR + ld4) = v;
    }
    if (tid < QROWS) { mrow[tid] = -1e30f; lrow[tid] = 0.f; }

    float accO[8][4];
#pragma unroll
    for (int ns = 0; ns < 8; ns++)
#pragma unroll
        for (int r = 0; r < 4; r++) accO[ns][r] = 0.f;

    const int nkb = 2 * qb + 2;   // number of 64-col K tiles

    // ---- preload K(0), V(0) ----
#pragma unroll
    for (int rr = 0; rr < KCOLS; rr += 16)
        cp_async16(Ks + (lr + rr) * AQSTR + ld4,
                   K + (size_t)(lr + rr) * KVD + kvh * HD + ld4);
    cp_commit();
#pragma unroll
    for (int rr = 0; rr < KCOLS; rr += 16)
        cp_async16(Vs + (lr + rr) * AVSTR + ld4,
                   V + (size_t)(lr + rr) * KVD + kvh * HD + ld4);
    cp_commit();

    for (int kb = 0; kb < nkb; kb++) {
        cp_wait1();          // K(kb) landed (V(kb) may still be in flight)
        __syncthreads();

        // ---- S = Qs @ K^T : warp tile 16x32 at (mi*16, nj*32) ----
        float cS[4][4];
#pragma unroll
        for (int ns = 0; ns < 4; ns++)
#pragma unroll
            for (int r = 0; r < 4; r++) cS[ns][r] = 0.f;

#pragma unroll
        for (int k8 = 0; k8 < HD; k8 += 8) {
            uint32_t a[4];
            a[0] = f2tf32(Qt[(mrow0)     * AQSTR + k8 + tg]);
            a[1] = f2tf32(Qt[(mrow0 + 8) * AQSTR + k8 + tg]);
            a[2] = f2tf32(Qt[(mrow0)     * AQSTR + k8 + tg + 4]);
            a[3] = f2tf32(Qt[(mrow0 + 8) * AQSTR + k8 + tg + 4]);
#pragma unroll
            for (int ns = 0; ns < 4; ns++) {
                const int c = nj * 32 + ns * 8 + g;
                uint32_t b[2];
                b[0] = f2tf32(Ks[c * AQSTR + k8 + tg]);
                b[1] = f2tf32(Ks[c * AQSTR + k8 + tg + 4]);
                mma_tf32(cS[ns], a, b);
            }
        }
#pragma unroll
        for (int ns = 0; ns < 4; ns++) {
            const int cc = nj * 32 + ns * 8 + 2 * tg;
            *(float2*)(Ss + (mrow0)     * ASSTR + cc) = make_float2(cS[ns][0], cS[ns][1]);
            *(float2*)(Ss + (mrow0 + 8) * ASSTR + cc) = make_float2(cS[ns][2], cS[ns][3]);
        }
        __syncthreads();     // S visible; K reads done -> Ks free

        // ---- issue K(kb+1) (overlaps softmax) ----
        if (kb + 1 < nkb) {
#pragma unroll
            for (int rr = 0; rr < KCOLS; rr += 16)
                cp_async16(Ks + (lr + rr) * AQSTR + ld4,
                           K + (size_t)((kb + 1) * KCOLS + lr + rr) * KVD + kvh * HD + ld4);
        }
        cp_commit();

        // ---- softmax: 4 threads per row ----
        {
            int lim = qb * QROWS + sr - kb * KCOLS + 1;
            lim = lim > KCOLS ? KCOLS : (lim < 0 ? 0 : lim);
            float* srow = Ss + sr * ASSTR + sq;
            float4 s0 = *(float4*)(srow);
            float4 s1 = *(float4*)(srow + 4);
            float4 s2 = *(float4*)(srow + 8);
            float4 s3 = *(float4*)(srow + 12);
            float sv[16] = {s0.x,s0.y,s0.z,s0.w, s1.x,s1.y,s1.z,s1.w,
                            s2.x,s2.y,s2.z,s2.w, s3.x,s3.y,s3.z,s3.w};
            float mx = -1e30f;
#pragma unroll
            for (int c = 0; c < 16; c++)
                if (sq + c < lim) mx = fmaxf(mx, sv[c]);
            mx = fmaxf(mx, __shfl_xor_sync(0xffffffffu, mx, 1));
            mx = fmaxf(mx, __shfl_xor_sync(0xffffffffu, mx, 2));
            float mold = mrow[sr];
            mx = fmaxf(mx, mold);
            float sum = 0.f;
#pragma unroll
            for (int c = 0; c < 16; c++) {
                float p = (sq + c < lim) ? __expf(sv[c] - mx) : 0.f;
                sv[c] = p;
                sum += p;
            }
            sum += __shfl_xor_sync(0xffffffffu, sum, 1);
            sum += __shfl_xor_sync(0xffffffffu, sum, 2);
            *(float4*)(srow)      = make_float4(sv[0],  sv[1],  sv[2],  sv[3]);
            *(float4*)(srow + 4)  = make_float4(sv[4],  sv[5],  sv[6],  sv[7]);
            *(float4*)(srow + 8)  = make_float4(sv[8],  sv[9],  sv[10], sv[11]);
            *(float4*)(srow + 12) = make_float4(sv[12], sv[13], sv[14], sv[15]);
            if ((tid & 3) == 0) {
                float alpha = __expf(mold - mx);
                mrow[sr] = mx;
                lrow[sr] = lrow[sr] * alpha + sum;
                arow[sr] = alpha;
            }
        }
        cp_wait1();          // V(kb) landed (K(kb+1) may still be in flight)
        __syncthreads();     // P + arow + V visible

        // ---- O = O*alpha + P @ V : warp tile 16x64 at (mi*16, nj*64) ----
        {
            float a0 = arow[mrow0], a1 = arow[mrow0 + 8];
#pragma unroll
            for (int ns = 0; ns < 8; ns++) {
                accO[ns][0] *= a0; accO[ns][1] *= a0;
                accO[ns][2] *= a1; accO[ns][3] *= a1;
            }
        }
#pragma unroll
        for (int k8 = 0; k8 < KCOLS; k8 += 8) {
            uint32_t ap[4];
            ap[0] = f2tf32(Ss[(mrow0)     * ASSTR + k8 + tg]);
            ap[1] = f2tf32(Ss[(mrow0 + 8) * ASSTR + k8 + tg]);
            ap[2] = f2tf32(Ss[(mrow0)     * ASSTR + k8 + tg + 4]);
            ap[3] = f2tf32(Ss[(mrow0 + 8) * ASSTR + k8 + tg + 4]);
#pragma unroll
            for (int ns = 0; ns < 8; ns++) {
                const int c = nj * 64 + ns * 8 + g;
                float v0 = Vs[(k8 + tg)     * AVSTR + c];
                float v1 = Vs[(k8 + tg + 4) * AVSTR + c];
                uint32_t bh[2], bl[2];
                bh[0] = __float_as_uint(v0) & 0xffffe000u;
                bh[1] = __float_as_uint(v1) & 0xffffe000u;
                bl[0] = __float_as_uint(v0 - __uint_as_float(bh[0]));
                bl[1] = __float_as_uint(v1 - __uint_as_float(bh[1]));
                mma_tf32(accO[ns], ap, bh);
                mma_tf32(accO[ns], ap, bl);
            }
        }
        __syncthreads();     // PV done -> Vs free

        // ---- issue V(kb+1) ----
        if (kb + 1 < nkb) {
#pragma unroll
            for (int rr = 0; rr < KCOLS; rr += 16)
                cp_async16(Vs + (lr + rr) * AVSTR + ld4,
                           V + (size_t)((kb + 1) * KCOLS + lr + rr) * KVD + kvh * HD + ld4);
        }
        cp_commit();
    }

    // ---- epilogue ----
    const float inv0 = 1.f / lrow[mrow0];
    const float inv1 = 1.f / lrow[mrow0 + 8];
#pragma unroll
    for (int ns = 0; ns < 8; ns++) {
        const int cc = h * HD + nj * 64 + ns * 8 + 2 * tg;
        float* op0 = O + (size_t)(qb * QROWS + mrow0) * QD + cc;
        float* op1 = O + (size_t)(qb * QROWS + mrow0 + 8) * QD + cc;
        *(float2*)op0 = make_float2(accO[ns][0] * inv0, accO[ns][1] * inv0);
        *(float2*)op1 = make_float2(accO[ns][2] * inv1, accO[ns][3] * inv1);
    }
}

// ---------------------------------------------------------------------------
// Launch
// ---------------------------------------------------------------------------
extern "C" void kernel_launch(void* const* d_in, const int* in_sizes, int n_in,
                              void* d_out, int out_size)
{
    (void)in_sizes; (void)n_in; (void)out_size;
    const float* x  = (const float*)d_in[0];
    const float* wq = (const float*)d_in[1];
    const float* wk = (const float*)d_in[2];
    const float* wv = (const float*)d_in[3];
    const float* wo = (const float*)d_in[4];
    const float* fc = (const float*)d_in[5];
    const float* fs = (const float*)d_in[6];
    float* out = (float*)d_out;

    float *q, *k, *v, *att;
    cudaGetSymbolAddress((void**)&q,   g_q);
    cudaGetSymbolAddress((void**)&k,   g_k);
    cudaGetSymbolAddress((void**)&v,   g_v);
    cudaGetSymbolAddress((void**)&att, g_att);

    cudaFuncSetAttribute(gemm_tf32,
                         cudaFuncAttributeMaxDynamicSharedMemorySize,
                         GEMM_SMEM_BYTES);
    cudaFuncSetAttribute(flash_attn_tc2,
                         cudaFuncAttributeMaxDynamicSharedMemorySize,
                         FA2_SMEM_BYTES);

    // QKV projections (tf32 tensor cores)
    gemm_tf32<<<dim3(QD / BN,  SEQ / BM), 256, GEMM_SMEM_BYTES>>>(x, wq, q, SEQ, QD,  DIMM);
    gemm_tf32<<<dim3(KVD / BN, SEQ / BM), 256, GEMM_SMEM_BYTES>>>(x, wk, k, SEQ, KVD, DIMM);
    gemm_tf32<<<dim3(KVD / BN, SEQ / BM), 256, GEMM_SMEM_BYTES>>>(x, wv, v, SEQ, KVD, DIMM);

    // RoPE
    int totq = SEQ * NHEADS * (HD / 2);
    int totk = SEQ * NKVH * (HD / 2);
    rope_kernel<<<(totq + 255) / 256, 256>>>(q, fc, fs, NHEADS, totq);
    rope_kernel<<<(totk + 255) / 256, 256>>>(k, fc, fs, NKVH, totk);

    // Fused causal attention (tensor cores, 128-row Q tiles)
    flash_attn_tc2<<<dim3(SEQ / QROWS, NHEADS), 512, FA2_SMEM_BYTES>>>(q, k, v, att);

    // Output projection
    gemm_tf32<<<dim3(DIMM / BN, SEQ / BM), 256, GEMM_SMEM_BYTES>>>(att, wo, out, SEQ, DIMM, QD);
}

// round 12
// speedup vs baseline: 1.0586x; 1.0586x over previous
#include <cuda_runtime.h>
#include <cstdint>

#define SEQ    2048
#define DIMM   4096
#define NHEADS 32
#define NKVH   8
#define HD     128
#define QD     (NHEADS * HD)   // 4096
#define KVD    (NKVH * HD)     // 1024

// Scratch (no cudaMalloc allowed)
__device__ float g_q[SEQ * QD];
__device__ float g_k[SEQ * KVD];
__device__ float g_v[SEQ * KVD];
__device__ float g_att[SEQ * QD];

__device__ __forceinline__ uint32_t f2tf32(float x) {
    uint32_t r;
    asm("cvt.rna.tf32.f32 %0, %1;" : "=r"(r) : "f"(x));
    return r;
}

__device__ __forceinline__ void mma_tf32(float* c, const uint32_t* a, const uint32_t* b) {
    asm volatile(
        "mma.sync.aligned.m16n8k8.row.col.f32.tf32.tf32.f32 "
        "{%0,%1,%2,%3}, {%4,%5,%6,%7}, {%8,%9}, {%0,%1,%2,%3};\n"
        : "+f"(c[0]), "+f"(c[1]), "+f"(c[2]), "+f"(c[3])
        : "r"(a[0]), "r"(a[1]), "r"(a[2]), "r"(a[3]),
          "r"(b[0]), "r"(b[1]));
}

__device__ __forceinline__ void cp_async16(void* smem_dst, const void* gmem_src) {
    uint32_t dst = (uint32_t)__cvta_generic_to_shared(smem_dst);
    asm volatile("cp.async.cg.shared.global [%0], [%1], 16;\n"
                 :: "r"(dst), "l"(gmem_src));
}
__device__ __forceinline__ void cp_commit() {
    asm volatile("cp.async.commit_group;\n");
}
__device__ __forceinline__ void cp_wait0() {
    asm volatile("cp.async.wait_group 0;\n");
}

// ===========================================================================
// TF32 tensor-core GEMM — 4-stage cp.async ring (unchanged)
// ===========================================================================
#define BM 128
#define BN 128
#define BK 32
#define ASTRIDE 36
#define BSTRIDE 136
#define STAGE_FLOATS (BM * ASTRIDE + BK * BSTRIDE)   // 8960
#define NSTAGE 4
#define GEMM_SMEM_BYTES (NSTAGE * STAGE_FLOATS * 4)  // 143360

__global__ __launch_bounds__(256, 1) void gemm_tf32(
    const float* __restrict__ A, const float* __restrict__ B,
    float* __restrict__ C, int M, int N, int K)
{
    extern __shared__ float sm[];

    const int tid = threadIdx.x;
    const int bx = blockIdx.x, by = blockIdx.y;

    const int arow0 = tid >> 3;
    const int acol4 = (tid & 7) << 2;
    const int brow0 = tid >> 5;
    const int bcol4 = (tid & 31) << 2;

    const int lane = tid & 31;
    const int warp = tid >> 5;
    const int wr = warp >> 2;
    const int wc = warp & 3;
    const int g  = lane >> 2;
    const int tg = lane & 3;
    const int morg = wr * 64;
    const int norg = wc * 32;

    const float* Ab = A + (size_t)by * BM * K;
    const float* Bb = B + (size_t)bx * BN;

    float acc[4][4][4];
#pragma unroll
    for (int mi = 0; mi < 4; mi++)
#pragma unroll
        for (int ni = 0; ni < 4; ni++)
#pragma unroll
            for (int r = 0; r < 4; r++) acc[mi][ni][r] = 0.f;

    const int nk = K / BK;

    auto load_stage = [&](int s, int k0) {
        float* As_ = sm + s * STAGE_FLOATS;
        float* Bs_ = As_ + BM * ASTRIDE;
#pragma unroll
        for (int r = 0; r < BM; r += 32)
            cp_async16(&As_[(arow0 + r) * ASTRIDE + acol4],
                       Ab + (size_t)(arow0 + r) * K + k0 + acol4);
#pragma unroll
        for (int r = 0; r < BK; r += 8)
            cp_async16(&Bs_[(brow0 + r) * BSTRIDE + bcol4],
                       Bb + (size_t)(k0 + brow0 + r) * N + bcol4);
        cp_commit();
    };

    load_stage(0, 0);
    load_stage(1, BK);
    load_stage(2, 2 * BK);

    for (int kt = 0; kt < nk; kt++) {
        asm volatile("cp.async.wait_group 2;\n");
        __syncthreads();
        if (kt + 3 < nk) load_stage((kt + 3) & (NSTAGE - 1), (kt + 3) * BK);
        else             cp_commit();

        const float* As_ = sm + (kt & (NSTAGE - 1)) * STAGE_FLOATS;
        const float* Bs_ = As_ + BM * ASTRIDE;

#pragma unroll
        for (int k8 = 0; k8 < BK; k8 += 8) {
            uint32_t af[4][4], bf[4][2];
#pragma unroll
            for (int mi = 0; mi < 4; mi++) {
                const int r = morg + mi * 16 + g;
                af[mi][0] = f2tf32(As_[(r)     * ASTRIDE + k8 + tg]);
                af[mi][1] = f2tf32(As_[(r + 8) * ASTRIDE + k8 + tg]);
                af[mi][2] = f2tf32(As_[(r)     * ASTRIDE + k8 + tg + 4]);
                af[mi][3] = f2tf32(As_[(r + 8) * ASTRIDE + k8 + tg + 4]);
            }
#pragma unroll
            for (int ni = 0; ni < 4; ni++) {
                const int c = norg + ni * 8 + g;
                bf[ni][0] = f2tf32(Bs_[(k8 + tg)     * BSTRIDE + c]);
                bf[ni][1] = f2tf32(Bs_[(k8 + tg + 4) * BSTRIDE + c]);
            }
#pragma unroll
            for (int mi = 0; mi < 4; mi++)
#pragma unroll
                for (int ni = 0; ni < 4; ni++)
                    mma_tf32(acc[mi][ni], af[mi], bf[ni]);
        }
    }

    float* Cb = C + (size_t)(by * BM) * N + bx * BN;
#pragma unroll
    for (int mi = 0; mi < 4; mi++) {
#pragma unroll
        for (int ni = 0; ni < 4; ni++) {
            const int r0 = morg + mi * 16 + g;
            const int c0 = norg + ni * 8 + tg * 2;
            *(float2*)(&Cb[(size_t)r0 * N + c0]) =
                make_float2(acc[mi][ni][0], acc[mi][ni][1]);
            *(float2*)(&Cb[(size_t)(r0 + 8) * N + c0]) =
                make_float2(acc[mi][ni][2], acc[mi][ni][3]);
        }
    }
}

// ---------------------------------------------------------------------------
// RoPE (interleaved pairs)
// ---------------------------------------------------------------------------
__global__ void rope_kernel(float* __restrict__ t,
                            const float* __restrict__ fc,
                            const float* __restrict__ fs,
                            int nheads, int total)
{
    int idx = blockIdx.x * blockDim.x + threadIdx.x;
    if (idx >= total) return;
    int p = idx & 63;
    int h = (idx >> 6) % nheads;
    int s = idx / (64 * nheads);
    float c  = fc[s * 64 + p];
    float sn = fs[s * 64 + p];
    float* base = t + (size_t)s * nheads * HD + h * HD + 2 * p;
    float re = base[0], im = base[1];
    base[0] = re * c - im * sn;
    base[1] = re * sn + im * c;
}

// ===========================================================================
// Tensor-core flash attention v3 (causal, GQA 4:1), 64-row tiles (R7 base).
// Instruction-thinned inner loops:
//  - Qt holds PRE-CONVERTED tf32 bits (rounding moved to load, bit-identical)
//  - softmax stores P as tf32 bits (PV A-loads are raw, bit-identical)
//  - PV uses a SINGLE tf32 MMA (V tf32-rounded; adds <1e-4 RMS error)
// ===========================================================================
#define QSTR 132
#define VSTR 136
#define SSTR 68
#define FA_Q_FLOATS   (64 * QSTR)
#define FA_KV_FLOATS  (64 * VSTR)
#define FA_S_FLOATS   (64 * SSTR)
#define FA_SMEM_FLOATS (FA_Q_FLOATS + FA_KV_FLOATS + FA_S_FLOATS + 192)
#define FA_SMEM_BYTES  (FA_SMEM_FLOATS * 4)   // 86784

__global__ __launch_bounds__(256, 2) void flash_attn_tc(
    const float* __restrict__ Q, const float* __restrict__ K,
    const float* __restrict__ V, float* __restrict__ O)
{
    extern __shared__ float sm[];
    float* Qt   = sm;                          // [64][QSTR]  (tf32 bits)
    float* KVs  = sm + FA_Q_FLOATS;            // K:[64][QSTR] or V:[64][VSTR]
    float* Ss   = KVs + FA_KV_FLOATS;          // [64][SSTR]  (S fp32, then P tf32 bits)
    float* mrow = Ss + FA_S_FLOATS;
    float* lrow = mrow + 64;
    float* arow = lrow + 64;

    const int tid  = threadIdx.x;
    const int qb   = blockIdx.x, h = blockIdx.y, kvh = h >> 2;
    const int lane = tid & 31;
    const int warp = tid >> 5;
    const int g    = lane >> 2;
    const int tg   = lane & 3;
    const int mi   = warp & 3;
    const int nj   = warp >> 2;
    const int lr   = tid >> 5;
    const int ld4  = (tid & 31) << 2;
    const float scale = 0.08838834764831845f;

    const int mrow0 = mi * 16 + g;

    const int sr = tid >> 2;          // softmax row 0..63
    const int sq = (tid & 3) << 4;    // softmax col base

    // ---- load Q tile: scale then pre-round to tf32 bits ----
#pragma unroll
    for (int rr = 0; rr < 64; rr += 8) {
        float4 v = *(const float4*)(Q + (size_t)(qb * 64 + lr + rr) * QD + h * HD + ld4);
        float4 w;
        w.x = __uint_as_float(f2tf32(v.x * scale));
        w.y = __uint_as_float(f2tf32(v.y * scale));
        w.z = __uint_as_float(f2tf32(v.z * scale));
        w.w = __uint_as_float(f2tf32(v.w * scale));
        *(float4*)(Qt + (lr + rr) * QSTR + ld4) = w;
    }
    if (tid < 64) { mrow[tid] = -1e30f; lrow[tid] = 0.f; }

    float accO[8][4];
#pragma unroll
    for (int ns = 0; ns < 8; ns++)
#pragma unroll
        for (int r = 0; r < 4; r++) accO[ns][r] = 0.f;

    // first K tile via cp.async
#pragma unroll
    for (int rr = 0; rr < 64; rr += 8)
        cp_async16(KVs + (lr + rr) * QSTR + ld4,
                   K + (size_t)(lr + rr) * KVD + kvh * HD + ld4);
    cp_commit();
    cp_wait0();
    __syncthreads();

    for (int kb = 0; kb <= qb; kb++) {
        // ---- S = Qs @ K^T : warp tile 16x32 at (mi*16, nj*32) ----
        float cS[4][4];
#pragma unroll
        for (int ns = 0; ns < 4; ns++)
#pragma unroll
            for (int r = 0; r < 4; r++) cS[ns][r] = 0.f;

#pragma unroll
        for (int k8 = 0; k8 < HD; k8 += 8) {
            uint32_t a[4];
            a[0] = __float_as_uint(Qt[(mrow0)     * QSTR + k8 + tg]);
            a[1] = __float_as_uint(Qt[(mrow0 + 8) * QSTR + k8 + tg]);
            a[2] = __float_as_uint(Qt[(mrow0)     * QSTR + k8 + tg + 4]);
            a[3] = __float_as_uint(Qt[(mrow0 + 8) * QSTR + k8 + tg + 4]);
#pragma unroll
            for (int ns = 0; ns < 4; ns++) {
                const int c = nj * 32 + ns * 8 + g;
                uint32_t b[2];
                b[0] = f2tf32(KVs[c * QSTR + k8 + tg]);
                b[1] = f2tf32(KVs[c * QSTR + k8 + tg + 4]);
                mma_tf32(cS[ns], a, b);
            }
        }
#pragma unroll
        for (int ns = 0; ns < 4; ns++) {
            const int cc = nj * 32 + ns * 8 + 2 * tg;
            *(float2*)(Ss + (mrow0)     * SSTR + cc) = make_float2(cS[ns][0], cS[ns][1]);
            *(float2*)(Ss + (mrow0 + 8) * SSTR + cc) = make_float2(cS[ns][2], cS[ns][3]);
        }
        __syncthreads();   // S visible; all K reads done

        // ---- V tile via cp.async (overlaps softmax) ----
#pragma unroll
        for (int rr = 0; rr < 64; rr += 8)
            cp_async16(KVs + (lr + rr) * VSTR + ld4,
                       V + (size_t)(kb * 64 + lr + rr) * KVD + kvh * HD + ld4);
        cp_commit();

        // ---- softmax: 4 threads per row; stores P as tf32 bits ----
        {
            const int lim = (kb == qb) ? (sr + 1) : 64;
            float* srow = Ss + sr * SSTR + sq;
            float4 s0 = *(float4*)(srow);
            float4 s1 = *(float4*)(srow + 4);
            float4 s2 = *(float4*)(srow + 8);
            float4 s3 = *(float4*)(srow + 12);
            float sv[16] = {s0.x,s0.y,s0.z,s0.w, s1.x,s1.y,s1.z,s1.w,
                            s2.x,s2.y,s2.z,s2.w, s3.x,s3.y,s3.z,s3.w};
            float mx = -1e30f;
#pragma unroll
            for (int c = 0; c < 16; c++)
                if (sq + c < lim) mx = fmaxf(mx, sv[c]);
            mx = fmaxf(mx, __shfl_xor_sync(0xffffffffu, mx, 1));
            mx = fmaxf(mx, __shfl_xor_sync(0xffffffffu, mx, 2));
            float mold = mrow[sr];
            mx = fmaxf(mx, mold);
            float sum = 0.f;
#pragma unroll
            for (int c = 0; c < 16; c++) {
                float p = (sq + c < lim) ? __expf(sv[c] - mx) : 0.f;
                p = __uint_as_float(f2tf32(p));   // pre-round for PV MMA
                sv[c] = p;
                sum += p;
            }
            sum += __shfl_xor_sync(0xffffffffu, sum, 1);
            sum += __shfl_xor_sync(0xffffffffu, sum, 2);
            *(float4*)(srow)      = make_float4(sv[0],  sv[1],  sv[2],  sv[3]);
            *(float4*)(srow + 4)  = make_float4(sv[4],  sv[5],  sv[6],  sv[7]);
            *(float4*)(srow + 8)  = make_float4(sv[8],  sv[9],  sv[10], sv[11]);
            *(float4*)(srow + 12) = make_float4(sv[12], sv[13], sv[14], sv[15]);
            if ((tid & 3) == 0) {
                float alpha = __expf(mold - mx);
                mrow[sr] = mx;
                lrow[sr] = lrow[sr] * alpha + sum;
                arow[sr] = alpha;
            }
        }
        cp_wait0();        // own V copies landed
        __syncthreads();   // everyone's V + P + arow visible

        // ---- O = O*alpha + P @ V : single tf32 MMA per fragment ----
        {
            float a0 = arow[mrow0], a1 = arow[mrow0 + 8];
#pragma unroll
            for (int ns = 0; ns < 8; ns++) {
                accO[ns][0] *= a0; accO[ns][1] *= a0;
                accO[ns][2] *= a1; accO[ns][3] *= a1;
            }
        }
#pragma unroll
        for (int k8 = 0; k8 < 64; k8 += 8) {
            uint32_t ap[4];
            ap[0] = __float_as_uint(Ss[(mrow0)     * SSTR + k8 + tg]);
            ap[1] = __float_as_uint(Ss[(mrow0 + 8) * SSTR + k8 + tg]);
            ap[2] = __float_as_uint(Ss[(mrow0)     * SSTR + k8 + tg + 4]);
            ap[3] = __float_as_uint(Ss[(mrow0 + 8) * SSTR + k8 + tg + 4]);
#pragma unroll
            for (int ns = 0; ns < 8; ns++) {
                const int c = nj * 64 + ns * 8 + g;
                uint32_t b[2];
                b[0] = f2tf32(KVs[(k8 + tg)     * VSTR + c]);
                b[1] = f2tf32(KVs[(k8 + tg + 4) * VSTR + c]);
                mma_tf32(accO[ns], ap, b);
            }
        }
        __syncthreads();   // PV done; KVs free

        // ---- next K tile via cp.async ----
        if (kb + 1 <= qb) {
#pragma unroll
            for (int rr = 0; rr < 64; rr += 8)
                cp_async16(KVs + (lr + rr) * QSTR + ld4,
                           K + (size_t)((kb + 1) * 64 + lr + rr) * KVD + kvh * HD + ld4);
            cp_commit();
            cp_wait0();
            __syncthreads();
        }
    }

    // ---- epilogue ----
    const float inv0 = 1.f / lrow[mrow0];
    const float inv1 = 1.f / lrow[mrow0 + 8];
#pragma unroll
    for (int ns = 0; ns < 8; ns++) {
        const int cc = h * HD + nj * 64 + ns * 8 + 2 * tg;
        float* op0 = O + (size_t)(qb * 64 + mrow0) * QD + cc;
        float* op1 = O + (size_t)(qb * 64 + mrow0 + 8) * QD + cc;
        *(float2*)op0 = make_float2(accO[ns][0] * inv0, accO[ns][1] * inv0);
        *(float2*)op1 = make_float2(accO[ns][2] * inv1, accO[ns][3] * inv1);
    }
}

// ---------------------------------------------------------------------------
// Launch
// ---------------------------------------------------------------------------
extern "C" void kernel_launch(void* const* d_in, const int* in_sizes, int n_in,
                              void* d_out, int out_size)
{
    (void)in_sizes; (void)n_in; (void)out_size;
    const float* x  = (const float*)d_in[0];
    const float* wq = (const float*)d_in[1];
    const float* wk = (const float*)d_in[2];
    const float* wv = (const float*)d_in[3];
    const float* wo = (const float*)d_in[4];
    const float* fc = (const float*)d_in[5];
    const float* fs = (const float*)d_in[6];
    float* out = (float*)d_out;

    float *q, *k, *v, *att;
    cudaGetSymbolAddress((void**)&q,   g_q);
    cudaGetSymbolAddress((void**)&k,   g_k);
    cudaGetSymbolAddress((void**)&v,   g_v);
    cudaGetSymbolAddress((void**)&att, g_att);

    cudaFuncSetAttribute(gemm_tf32,
                         cudaFuncAttributeMaxDynamicSharedMemorySize,
                         GEMM_SMEM_BYTES);
    cudaFuncSetAttribute(flash_attn_tc,
                         cudaFuncAttributeMaxDynamicSharedMemorySize,
                         FA_SMEM_BYTES);

    // QKV projections (tf32 tensor cores)
    gemm_tf32<<<dim3(QD / BN,  SEQ / BM), 256, GEMM_SMEM_BYTES>>>(x, wq, q, SEQ, QD,  DIMM);
    gemm_tf32<<<dim3(KVD / BN, SEQ / BM), 256, GEMM_SMEM_BYTES>>>(x, wk, k, SEQ, KVD, DIMM);
    gemm_tf32<<<dim3(KVD / BN, SEQ / BM), 256, GEMM_SMEM_BYTES>>>(x, wv, v, SEQ, KVD, DIMM);

    // RoPE
    int totq = SEQ * NHEADS * (HD / 2);
    int totk = SEQ * NKVH * (HD / 2);
    rope_kernel<<<(totq + 255) / 256, 256>>>(q, fc, fs, NHEADS, totq);
    rope_kernel<<<(totk + 255) / 256, 256>>>(k, fc, fs, NKVH, totk);

    // Fused causal attention (tensor cores)
    flash_attn_tc<<<dim3(SEQ / 64, NHEADS), 256, FA_SMEM_BYTES>>>(q, k, v, att);

    // Output projection
    gemm_tf32<<<dim3(DIMM / BN, SEQ / BM), 256, GEMM_SMEM_BYTES>>>(att, wo, out, SEQ, DIMM, QD);
}

// round 13
// speedup vs baseline: 1.1409x; 1.0777x over previous
#include <cuda_runtime.h>
#include <cstdint>

#define SEQ    2048
#define DIMM   4096
#define NHEADS 32
#define NKVH   8
#define HD     128
#define QD     (NHEADS * HD)   // 4096
#define KVD    (NKVH * HD)     // 1024

// Scratch (no cudaMalloc allowed)
__device__ float g_q[SEQ * QD];
__device__ float g_k[SEQ * KVD];
__device__ float g_v[SEQ * KVD];
__device__ float g_att[SEQ * QD];   // holds x_tf32 before flash, att after

__device__ __forceinline__ uint32_t f2tf32(float x) {
    uint32_t r;
    asm("cvt.rna.tf32.f32 %0, %1;" : "=r"(r) : "f"(x));
    return r;
}

__device__ __forceinline__ void mma_tf32(float* c, const uint32_t* a, const uint32_t* b) {
    asm volatile(
        "mma.sync.aligned.m16n8k8.row.col.f32.tf32.tf32.f32 "
        "{%0,%1,%2,%3}, {%4,%5,%6,%7}, {%8,%9}, {%0,%1,%2,%3};\n"
        : "+f"(c[0]), "+f"(c[1]), "+f"(c[2]), "+f"(c[3])
        : "r"(a[0]), "r"(a[1]), "r"(a[2]), "r"(a[3]),
          "r"(b[0]), "r"(b[1]));
}

__device__ __forceinline__ void cp_async16(void* smem_dst, const void* gmem_src) {
    uint32_t dst = (uint32_t)__cvta_generic_to_shared(smem_dst);
    asm volatile("cp.async.cg.shared.global [%0], [%1], 16;\n"
                 :: "r"(dst), "l"(gmem_src));
}
__device__ __forceinline__ void cp_commit() {
    asm volatile("cp.async.commit_group;\n");
}
__device__ __forceinline__ void cp_wait0() {
    asm volatile("cp.async.wait_group 0;\n");
}

// ---------------------------------------------------------------------------
// Elementwise tf32 pre-round (float4)
// ---------------------------------------------------------------------------
__global__ void cvt_tf32_kernel(const float* __restrict__ in,
                                float* __restrict__ out, int n4)
{
    int i = blockIdx.x * blockDim.x + threadIdx.x;
    if (i >= n4) return;
    float4 v = ((const float4*)in)[i];
    float4 w;
    w.x = __uint_as_float(f2tf32(v.x));
    w.y = __uint_as_float(f2tf32(v.y));
    w.z = __uint_as_float(f2tf32(v.z));
    w.w = __uint_as_float(f2tf32(v.w));
    ((float4*)out)[i] = w;
}

// ===========================================================================
// TF32 tensor-core GEMM — 4-stage cp.async ring.
// PRE_A:  A already tf32-rounded (skip CVT on A fragments)
// RND_C:  round C to tf32 bits at store (for V, consumed raw by PV)
// ===========================================================================
#define BM 128
#define BN 128
#define BK 32
#define ASTRIDE 36
#define BSTRIDE 136
#define STAGE_FLOATS (BM * ASTRIDE + BK * BSTRIDE)   // 8960
#define NSTAGE 4
#define GEMM_SMEM_BYTES (NSTAGE * STAGE_FLOATS * 4)  // 143360

template<bool PRE_A, bool RND_C>
__global__ __launch_bounds__(256, 1) void gemm_tf32(
    const float* __restrict__ A, const float* __restrict__ B,
    float* __restrict__ C, int M, int N, int K)
{
    extern __shared__ float sm[];

    const int tid = threadIdx.x;
    const int bx = blockIdx.x, by = blockIdx.y;

    const int arow0 = tid >> 3;
    const int acol4 = (tid & 7) << 2;
    const int brow0 = tid >> 5;
    const int bcol4 = (tid & 31) << 2;

    const int lane = tid & 31;
    const int warp = tid >> 5;
    const int wr = warp >> 2;
    const int wc = warp & 3;
    const int g  = lane >> 2;
    const int tg = lane & 3;
    const int morg = wr * 64;
    const int norg = wc * 32;

    const float* Ab = A + (size_t)by * BM * K;
    const float* Bb = B + (size_t)bx * BN;

    float acc[4][4][4];
#pragma unroll
    for (int mi = 0; mi < 4; mi++)
#pragma unroll
        for (int ni = 0; ni < 4; ni++)
#pragma unroll
            for (int r = 0; r < 4; r++) acc[mi][ni][r] = 0.f;

    const int nk = K / BK;

    auto load_stage = [&](int s, int k0) {
        float* As_ = sm + s * STAGE_FLOATS;
        float* Bs_ = As_ + BM * ASTRIDE;
#pragma unroll
        for (int r = 0; r < BM; r += 32)
            cp_async16(&As_[(arow0 + r) * ASTRIDE + acol4],
                       Ab + (size_t)(arow0 + r) * K + k0 + acol4);
#pragma unroll
        for (int r = 0; r < BK; r += 8)
            cp_async16(&Bs_[(brow0 + r) * BSTRIDE + bcol4],
                       Bb + (size_t)(k0 + brow0 + r) * N + bcol4);
        cp_commit();
    };

    load_stage(0, 0);
    load_stage(1, BK);
    load_stage(2, 2 * BK);

    for (int kt = 0; kt < nk; kt++) {
        asm volatile("cp.async.wait_group 2;\n");
        __syncthreads();
        if (kt + 3 < nk) load_stage((kt + 3) & (NSTAGE - 1), (kt + 3) * BK);
        else             cp_commit();

        const float* As_ = sm + (kt & (NSTAGE - 1)) * STAGE_FLOATS;
        const float* Bs_ = As_ + BM * ASTRIDE;

#pragma unroll
        for (int k8 = 0; k8 < BK; k8 += 8) {
            uint32_t af[4][4], bf[4][2];
#pragma unroll
            for (int mi = 0; mi < 4; mi++) {
                const int r = morg + mi * 16 + g;
                if (PRE_A) {
                    af[mi][0] = __float_as_uint(As_[(r)     * ASTRIDE + k8 + tg]);
                    af[mi][1] = __float_as_uint(As_[(r + 8) * ASTRIDE + k8 + tg]);
                    af[mi][2] = __float_as_uint(As_[(r)     * ASTRIDE + k8 + tg + 4]);
                    af[mi][3] = __float_as_uint(As_[(r + 8) * ASTRIDE + k8 + tg + 4]);
                } else {
                    af[mi][0] = f2tf32(As_[(r)     * ASTRIDE + k8 + tg]);
                    af[mi][1] = f2tf32(As_[(r + 8) * ASTRIDE + k8 + tg]);
                    af[mi][2] = f2tf32(As_[(r)     * ASTRIDE + k8 + tg + 4]);
                    af[mi][3] = f2tf32(As_[(r + 8) * ASTRIDE + k8 + tg + 4]);
                }
            }
#pragma unroll
            for (int ni = 0; ni < 4; ni++) {
                const int c = norg + ni * 8 + g;
                bf[ni][0] = f2tf32(Bs_[(k8 + tg)     * BSTRIDE + c]);
                bf[ni][1] = f2tf32(Bs_[(k8 + tg + 4) * BSTRIDE + c]);
            }
#pragma unroll
            for (int mi = 0; mi < 4; mi++)
#pragma unroll
                for (int ni = 0; ni < 4; ni++)
                    mma_tf32(acc[mi][ni], af[mi], bf[ni]);
        }
    }

    float* Cb = C + (size_t)(by * BM) * N + bx * BN;
#pragma unroll
    for (int mi = 0; mi < 4; mi++) {
#pragma unroll
        for (int ni = 0; ni < 4; ni++) {
            const int r0 = morg + mi * 16 + g;
            const int c0 = norg + ni * 8 + tg * 2;
            float o0 = acc[mi][ni][0], o1 = acc[mi][ni][1];
            float o2 = acc[mi][ni][2], o3 = acc[mi][ni][3];
            if (RND_C) {
                o0 = __uint_as_float(f2tf32(o0));
                o1 = __uint_as_float(f2tf32(o1));
                o2 = __uint_as_float(f2tf32(o2));
                o3 = __uint_as_float(f2tf32(o3));
            }
            *(float2*)(&Cb[(size_t)r0 * N + c0])       = make_float2(o0, o1);
            *(float2*)(&Cb[(size_t)(r0 + 8) * N + c0]) = make_float2(o2, o3);
        }
    }
}

// ---------------------------------------------------------------------------
// RoPE (interleaved pairs); RND pre-rounds output to tf32 bits (for K)
// ---------------------------------------------------------------------------
template<bool RND>
__global__ void rope_kernel(float* __restrict__ t,
                            const float* __restrict__ fc,
                            const float* __restrict__ fs,
                            int nheads, int total)
{
    int idx = blockIdx.x * blockDim.x + threadIdx.x;
    if (idx >= total) return;
    int p = idx & 63;
    int h = (idx >> 6) % nheads;
    int s = idx / (64 * nheads);
    float c  = fc[s * 64 + p];
    float sn = fs[s * 64 + p];
    float* base = t + (size_t)s * nheads * HD + h * HD + 2 * p;
    float re = base[0], im = base[1];
    float o0 = re * c - im * sn;
    float o1 = re * sn + im * c;
    if (RND) {
        o0 = __uint_as_float(f2tf32(o0));
        o1 = __uint_as_float(f2tf32(o1));
    }
    base[0] = o0;
    base[1] = o1;
}

// ===========================================================================
// Tensor-core flash attention v4 (causal, GQA 4:1), 64-row tiles.
// ZERO CVTs in the MMA inner loops:
//  - Qt pre-rounded at tile load; K pre-rounded by rope; P rounded in softmax;
//  - V pre-rounded by the wv GEMM epilogue.
// Epilogue writes att pre-rounded (consumed raw by out-proj PRE_A).
// ===========================================================================
#define QSTR 132
#define VSTR 136
#define SSTR 68
#define FA_Q_FLOATS   (64 * QSTR)
#define FA_KV_FLOATS  (64 * VSTR)
#define FA_S_FLOATS   (64 * SSTR)
#define FA_SMEM_FLOATS (FA_Q_FLOATS + FA_KV_FLOATS + FA_S_FLOATS + 192)
#define FA_SMEM_BYTES  (FA_SMEM_FLOATS * 4)   // 86784

__global__ __launch_bounds__(256, 2) void flash_attn_tc(
    const float* __restrict__ Q, const float* __restrict__ K,
    const float* __restrict__ V, float* __restrict__ O)
{
    extern __shared__ float sm[];
    float* Qt   = sm;                          // [64][QSTR]  (tf32 bits)
    float* KVs  = sm + FA_Q_FLOATS;            // K or V (both tf32 bits)
    float* Ss   = KVs + FA_KV_FLOATS;          // [64][SSTR]
    float* mrow = Ss + FA_S_FLOATS;
    float* lrow = mrow + 64;
    float* arow = lrow + 64;

    const int tid  = threadIdx.x;
    const int qb   = blockIdx.x, h = blockIdx.y, kvh = h >> 2;
    const int lane = tid & 31;
    const int warp = tid >> 5;
    const int g    = lane >> 2;
    const int tg   = lane & 3;
    const int mi   = warp & 3;
    const int nj   = warp >> 2;
    const int lr   = tid >> 5;
    const int ld4  = (tid & 31) << 2;
    const float scale = 0.08838834764831845f;

    const int mrow0 = mi * 16 + g;

    const int sr = tid >> 2;
    const int sq = (tid & 3) << 4;

    // ---- load Q tile: scale then pre-round to tf32 bits ----
#pragma unroll
    for (int rr = 0; rr < 64; rr += 8) {
        float4 v = *(const float4*)(Q + (size_t)(qb * 64 + lr + rr) * QD + h * HD + ld4);
        float4 w;
        w.x = __uint_as_float(f2tf32(v.x * scale));
        w.y = __uint_as_float(f2tf32(v.y * scale));
        w.z = __uint_as_float(f2tf32(v.z * scale));
        w.w = __uint_as_float(f2tf32(v.w * scale));
        *(float4*)(Qt + (lr + rr) * QSTR + ld4) = w;
    }
    if (tid < 64) { mrow[tid] = -1e30f; lrow[tid] = 0.f; }

    float accO[8][4];
#pragma unroll
    for (int ns = 0; ns < 8; ns++)
#pragma unroll
        for (int r = 0; r < 4; r++) accO[ns][r] = 0.f;

    // first K tile via cp.async
#pragma unroll
    for (int rr = 0; rr < 64; rr += 8)
        cp_async16(KVs + (lr + rr) * QSTR + ld4,
                   K + (size_t)(lr + rr) * KVD + kvh * HD + ld4);
    cp_commit();
    cp_wait0();
    __syncthreads();

    for (int kb = 0; kb <= qb; kb++) {
        // ---- S = Qs @ K^T (all operands pre-rounded) ----
        float cS[4][4];
#pragma unroll
        for (int ns = 0; ns < 4; ns++)
#pragma unroll
            for (int r = 0; r < 4; r++) cS[ns][r] = 0.f;

#pragma unroll
        for (int k8 = 0; k8 < HD; k8 += 8) {
            uint32_t a[4];
            a[0] = __float_as_uint(Qt[(mrow0)     * QSTR + k8 + tg]);
            a[1] = __float_as_uint(Qt[(mrow0 + 8) * QSTR + k8 + tg]);
            a[2] = __float_as_uint(Qt[(mrow0)     * QSTR + k8 + tg + 4]);
            a[3] = __float_as_uint(Qt[(mrow0 + 8) * QSTR + k8 + tg + 4]);
#pragma unroll
            for (int ns = 0; ns < 4; ns++) {
                const int c = nj * 32 + ns * 8 + g;
                uint32_t b[2];
                b[0] = __float_as_uint(KVs[c * QSTR + k8 + tg]);
                b[1] = __float_as_uint(KVs[c * QSTR + k8 + tg + 4]);
                mma_tf32(cS[ns], a, b);
            }
        }
#pragma unroll
        for (int ns = 0; ns < 4; ns++) {
            const int cc = nj * 32 + ns * 8 + 2 * tg;
            *(float2*)(Ss + (mrow0)     * SSTR + cc) = make_float2(cS[ns][0], cS[ns][1]);
            *(float2*)(Ss + (mrow0 + 8) * SSTR + cc) = make_float2(cS[ns][2], cS[ns][3]);
        }
        __syncthreads();

        // ---- V tile via cp.async (overlaps softmax) ----
#pragma unroll
        for (int rr = 0; rr < 64; rr += 8)
            cp_async16(KVs + (lr + rr) * VSTR + ld4,
                       V + (size_t)(kb * 64 + lr + rr) * KVD + kvh * HD + ld4);
        cp_commit();

        // ---- softmax: 4 threads per row; stores P as tf32 bits ----
        {
            const int lim = (kb == qb) ? (sr + 1) : 64;
            float* srow = Ss + sr * SSTR + sq;
            float4 s0 = *(float4*)(srow);
            float4 s1 = *(float4*)(srow + 4);
            float4 s2 = *(float4*)(srow + 8);
            float4 s3 = *(float4*)(srow + 12);
            float sv[16] = {s0.x,s0.y,s0.z,s0.w, s1.x,s1.y,s1.z,s1.w,
                            s2.x,s2.y,s2.z,s2.w, s3.x,s3.y,s3.z,s3.w};
            float mx = -1e30f;
#pragma unroll
            for (int c = 0; c < 16; c++)
                if (sq + c < lim) mx = fmaxf(mx, sv[c]);
            mx = fmaxf(mx, __shfl_xor_sync(0xffffffffu, mx, 1));
            mx = fmaxf(mx, __shfl_xor_sync(0xffffffffu, mx, 2));
            float mold = mrow[sr];
            mx = fmaxf(mx, mold);
            float sum = 0.f;
#pragma unroll
            for (int c = 0; c < 16; c++) {
                float p = (sq + c < lim) ? __expf(sv[c] - mx) : 0.f;
                p = __uint_as_float(f2tf32(p));
                sv[c] = p;
                sum += p;
            }
            sum += __shfl_xor_sync(0xffffffffu, sum, 1);
            sum += __shfl_xor_sync(0xffffffffu, sum, 2);
            *(float4*)(srow)      = make_float4(sv[0],  sv[1],  sv[2],  sv[3]);
            *(float4*)(srow + 4)  = make_float4(sv[4],  sv[5],  sv[6],  sv[7]);
            *(float4*)(srow + 8)  = make_float4(sv[8],  sv[9],  sv[10], sv[11]);
            *(float4*)(srow + 12) = make_float4(sv[12], sv[13], sv[14], sv[15]);
            if ((tid & 3) == 0) {
                float alpha = __expf(mold - mx);
                mrow[sr] = mx;
                lrow[sr] = lrow[sr] * alpha + sum;
                arow[sr] = alpha;
            }
        }
        cp_wait0();
        __syncthreads();

        // ---- O = O*alpha + P @ V (all operands pre-rounded) ----
        {
            float a0 = arow[mrow0], a1 = arow[mrow0 + 8];
#pragma unroll
            for (int ns = 0; ns < 8; ns++) {
                accO[ns][0] *= a0; accO[ns][1] *= a0;
                accO[ns][2] *= a1; accO[ns][3] *= a1;
            }
        }
#pragma unroll
        for (int k8 = 0; k8 < 64; k8 += 8) {
            uint32_t ap[4];
            ap[0] = __float_as_uint(Ss[(mrow0)     * SSTR + k8 + tg]);
            ap[1] = __float_as_uint(Ss[(mrow0 + 8) * SSTR + k8 + tg]);
            ap[2] = __float_as_uint(Ss[(mrow0)     * SSTR + k8 + tg + 4]);
            ap[3] = __float_as_uint(Ss[(mrow0 + 8) * SSTR + k8 + tg + 4]);
#pragma unroll
            for (int ns = 0; ns < 8; ns++) {
                const int c = nj * 64 + ns * 8 + g;
                uint32_t b[2];
                b[0] = __float_as_uint(KVs[(k8 + tg)     * VSTR + c]);
                b[1] = __float_as_uint(KVs[(k8 + tg + 4) * VSTR + c]);
                mma_tf32(accO[ns], ap, b);
            }
        }
        __syncthreads();

        // ---- next K tile via cp.async ----
        if (kb + 1 <= qb) {
#pragma unroll
            for (int rr = 0; rr < 64; rr += 8)
                cp_async16(KVs + (lr + rr) * QSTR + ld4,
                           K + (size_t)((kb + 1) * 64 + lr + rr) * KVD + kvh * HD + ld4);
            cp_commit();
            cp_wait0();
            __syncthreads();
        }
    }

    // ---- epilogue: normalize, pre-round for out-proj, store ----
    const float inv0 = 1.f / lrow[mrow0];
    const float inv1 = 1.f / lrow[mrow0 + 8];
#pragma unroll
    for (int ns = 0; ns < 8; ns++) {
        const int cc = h * HD + nj * 64 + ns * 8 + 2 * tg;
        float* op0 = O + (size_t)(qb * 64 + mrow0) * QD + cc;
        float* op1 = O + (size_t)(qb * 64 + mrow0 + 8) * QD + cc;
        *(float2*)op0 = make_float2(__uint_as_float(f2tf32(accO[ns][0] * inv0)),
                                    __uint_as_float(f2tf32(accO[ns][1] * inv0)));
        *(float2*)op1 = make_float2(__uint_as_float(f2tf32(accO[ns][2] * inv1)),
                                    __uint_as_float(f2tf32(accO[ns][3] * inv1)));
    }
}

// ---------------------------------------------------------------------------
// Launch
// ---------------------------------------------------------------------------
extern "C" void kernel_launch(void* const* d_in, const int* in_sizes, int n_in,
                              void* d_out, int out_size)
{
    (void)in_sizes; (void)n_in; (void)out_size;
    const float* x  = (const float*)d_in[0];
    const float* wq = (const float*)d_in[1];
    const float* wk = (const float*)d_in[2];
    const float* wv = (const float*)d_in[3];
    const float* wo = (const float*)d_in[4];
    const float* fc = (const float*)d_in[5];
    const float* fs = (const float*)d_in[6];
    float* out = (float*)d_out;

    float *q, *k, *v, *att;
    cudaGetSymbolAddress((void**)&q,   g_q);
    cudaGetSymbolAddress((void**)&k,   g_k);
    cudaGetSymbolAddress((void**)&v,   g_v);
    cudaGetSymbolAddress((void**)&att, g_att);

    cudaFuncSetAttribute(gemm_tf32<true, false>,
                         cudaFuncAttributeMaxDynamicSharedMemorySize, GEMM_SMEM_BYTES);
    cudaFuncSetAttribute(gemm_tf32<true, true>,
                         cudaFuncAttributeMaxDynamicSharedMemorySize, GEMM_SMEM_BYTES);
    cudaFuncSetAttribute(flash_attn_tc,
                         cudaFuncAttributeMaxDynamicSharedMemorySize, FA_SMEM_BYTES);

    // Pre-round x into g_att (free until flash writes att)
    int n4 = SEQ * DIMM / 4;
    cvt_tf32_kernel<<<(n4 + 255) / 256, 256>>>(x, att, n4);

    // QKV projections (A pre-rounded; V output rounded for PV)
    gemm_tf32<true, false><<<dim3(QD / BN,  SEQ / BM), 256, GEMM_SMEM_BYTES>>>(att, wq, q, SEQ, QD,  DIMM);
    gemm_tf32<true, false><<<dim3(KVD / BN, SEQ / BM), 256, GEMM_SMEM_BYTES>>>(att, wk, k, SEQ, KVD, DIMM);
    gemm_tf32<true, true ><<<dim3(KVD / BN, SEQ / BM), 256, GEMM_SMEM_BYTES>>>(att, wv, v, SEQ, KVD, DIMM);

    // RoPE (K output pre-rounded to tf32)
    int totq = SEQ * NHEADS * (HD / 2);
    int totk = SEQ * NKVH * (HD / 2);
    rope_kernel<false><<<(totq + 255) / 256, 256>>>(q, fc, fs, NHEADS, totq);
    rope_kernel<true ><<<(totk + 255) / 256, 256>>>(k, fc, fs, NKVH, totk);

    // Fused causal attention (writes att pre-rounded)
    flash_attn_tc<<<dim3(SEQ / 64, NHEADS), 256, FA_SMEM_BYTES>>>(q, k, v, att);

    // Output projection (A = att, pre-rounded)
    gemm_tf32<true, false><<<dim3(DIMM / BN, SEQ / BM), 256, GEMM_SMEM_BYTES>>>(att, wo, out, SEQ, DIMM, QD);
}

// round 17
// speedup vs baseline: 1.2117x; 1.0621x over previous
#include <cuda_runtime.h>
#include <cstdint>

#define SEQ    2048
#define DIMM   4096
#define NHEADS 32
#define NKVH   8
#define HD     128
#define QD     (NHEADS * HD)   // 4096
#define KVD    (NKVH * HD)     // 1024

// Scratch (no cudaMalloc allowed)
__device__ float g_q[SEQ * QD];
__device__ float g_k[SEQ * KVD];
__device__ float g_v[SEQ * KVD];
__device__ float g_att[SEQ * QD];     // x_tf32 before flash, att after
__device__ float g_wq[DIMM * QD];     // tf32-rounded weights
__device__ float g_wk[DIMM * KVD];
__device__ float g_wv[DIMM * KVD];
__device__ float g_wo[QD * DIMM];

__device__ __forceinline__ uint32_t f2tf32(float x) {
    uint32_t r;
    asm("cvt.rna.tf32.f32 %0, %1;" : "=r"(r) : "f"(x));
    return r;
}

__device__ __forceinline__ void mma_tf32(float* c, const uint32_t* a, const uint32_t* b) {
    asm volatile(
        "mma.sync.aligned.m16n8k8.row.col.f32.tf32.tf32.f32 "
        "{%0,%1,%2,%3}, {%4,%5,%6,%7}, {%8,%9}, {%0,%1,%2,%3};\n"
        : "+f"(c[0]), "+f"(c[1]), "+f"(c[2]), "+f"(c[3])
        : "r"(a[0]), "r"(a[1]), "r"(a[2]), "r"(a[3]),
          "r"(b[0]), "r"(b[1]));
}

__device__ __forceinline__ void cp_async16(void* smem_dst, const void* gmem_src) {
    uint32_t dst = (uint32_t)__cvta_generic_to_shared(smem_dst);
    asm volatile("cp.async.cg.shared.global [%0], [%1], 16;\n"
                 :: "r"(dst), "l"(gmem_src));
}
__device__ __forceinline__ void cp_commit() {
    asm volatile("cp.async.commit_group;\n");
}
__device__ __forceinline__ void cp_wait0() {
    asm volatile("cp.async.wait_group 0;\n");
}

// ---------------------------------------------------------------------------
// Elementwise tf32 pre-round (float4)
// ---------------------------------------------------------------------------
__global__ void cvt_tf32_kernel(const float* __restrict__ in,
                                float* __restrict__ out, int n4)
{
    int i = blockIdx.x * blockDim.x + threadIdx.x;
    if (i >= n4) return;
    float4 v = ((const float4*)in)[i];
    float4 w;
    w.x = __uint_as_float(f2tf32(v.x));
    w.y = __uint_as_float(f2tf32(v.y));
    w.z = __uint_as_float(f2tf32(v.z));
    w.w = __uint_as_float(f2tf32(v.w));
    ((float4*)out)[i] = w;
}

// ===========================================================================
// TF32 GEMM core — 2-stage cp.async ring, 2 CTAs/SM, pre-rounded A and B
// (zero CVTs in the inner loop).
// ===========================================================================
#define BM 128
#define BN 128
#define BK 32
#define ASTRIDE 36
#define BSTRIDE 136
#define STAGE_FLOATS (BM * ASTRIDE + BK * BSTRIDE)   // 8960
#define GEMM_SMEM_BYTES (2 * STAGE_FLOATS * 4)       // 71680

struct GemmMaps {
    int arow0, acol4, brow0, bcol4;
    int g, tg, morg, norg;
};

__device__ __forceinline__ GemmMaps make_maps(int tid) {
    GemmMaps mp;
    mp.arow0 = tid >> 3;
    mp.acol4 = (tid & 7) << 2;
    mp.brow0 = tid >> 5;
    mp.bcol4 = (tid & 31) << 2;
    int lane = tid & 31, warp = tid >> 5;
    mp.g  = lane >> 2;
    mp.tg = lane & 3;
    mp.morg = (warp >> 2) * 64;
    mp.norg = (warp & 3) * 32;
    return mp;
}

// core: A row-major [*, K], B row-major [K, N], C row-major [*, N]
__device__ __forceinline__ void gemm_body(
    const GemmMaps& mp, float* sm,
    const float* Ab, const float* Bb, float* Cb,
    int N, int K, bool rnd_c)
{
    float acc[4][4][4];
#pragma unroll
    for (int mi = 0; mi < 4; mi++)
#pragma unroll
        for (int ni = 0; ni < 4; ni++)
#pragma unroll
            for (int r = 0; r < 4; r++) acc[mi][ni][r] = 0.f;

    const int nk = K / BK;

    auto load_stage = [&](int s, int k0) {
        float* As_ = sm + s * STAGE_FLOATS;
        float* Bs_ = As_ + BM * ASTRIDE;
#pragma unroll
        for (int r = 0; r < BM; r += 32)
            cp_async16(&As_[(mp.arow0 + r) * ASTRIDE + mp.acol4],
                       Ab + (size_t)(mp.arow0 + r) * K + k0 + mp.acol4);
#pragma unroll
        for (int r = 0; r < BK; r += 8)
            cp_async16(&Bs_[(mp.brow0 + r) * BSTRIDE + mp.bcol4],
                       Bb + (size_t)(k0 + mp.brow0 + r) * N + mp.bcol4);
        cp_commit();
    };

    load_stage(0, 0);

    for (int kt = 0; kt < nk; kt++) {
        cp_wait0();
        __syncthreads();
        if (kt + 1 < nk) load_stage((kt + 1) & 1, (kt + 1) * BK);

        const float* As_ = sm + (kt & 1) * STAGE_FLOATS;
        const float* Bs_ = As_ + BM * ASTRIDE;

#pragma unroll
        for (int k8 = 0; k8 < BK; k8 += 8) {
            uint32_t af[4][4], bf[4][2];
#pragma unroll
            for (int mi = 0; mi < 4; mi++) {
                const int r = mp.morg + mi * 16 + mp.g;
                af[mi][0] = __float_as_uint(As_[(r)     * ASTRIDE + k8 + mp.tg]);
                af[mi][1] = __float_as_uint(As_[(r + 8) * ASTRIDE + k8 + mp.tg]);
                af[mi][2] = __float_as_uint(As_[(r)     * ASTRIDE + k8 + mp.tg + 4]);
                af[mi][3] = __float_as_uint(As_[(r + 8) * ASTRIDE + k8 + mp.tg + 4]);
            }
#pragma unroll
            for (int ni = 0; ni < 4; ni++) {
                const int c = mp.norg + ni * 8 + mp.g;
                bf[ni][0] = __float_as_uint(Bs_[(k8 + mp.tg)     * BSTRIDE + c]);
                bf[ni][1] = __float_as_uint(Bs_[(k8 + mp.tg + 4) * BSTRIDE + c]);
            }
#pragma unroll
            for (int mi = 0; mi < 4; mi++)
#pragma unroll
                for (int ni = 0; ni < 4; ni++)
                    mma_tf32(acc[mi][ni], af[mi], bf[ni]);
        }
        __syncthreads();
    }

#pragma unroll
    for (int mi = 0; mi < 4; mi++) {
#pragma unroll
        for (int ni = 0; ni < 4; ni++) {
            const int r0 = mp.morg + mi * 16 + mp.g;
            const int c0 = mp.norg + ni * 8 + mp.tg * 2;
            float o0 = acc[mi][ni][0], o1 = acc[mi][ni][1];
            float o2 = acc[mi][ni][2], o3 = acc[mi][ni][3];
            if (rnd_c) {
                o0 = __uint_as_float(f2tf32(o0));
                o1 = __uint_as_float(f2tf32(o1));
                o2 = __uint_as_float(f2tf32(o2));
                o3 = __uint_as_float(f2tf32(o3));
            }
            *(float2*)(&Cb[(size_t)r0 * N + c0])       = make_float2(o0, o1);
            *(float2*)(&Cb[(size_t)(r0 + 8) * N + c0]) = make_float2(o2, o3);
        }
    }
}

// Fused QKV projection: one launch, 48 x 16 CTA grid.
// bx 0..31 -> Q (N=4096), 32..39 -> K (N=1024), 40..47 -> V (N=1024, rounded C)
__global__ __launch_bounds__(256, 2) void gemm_qkv(
    const float* __restrict__ A,
    const float* __restrict__ Bq, const float* __restrict__ Bk, const float* __restrict__ Bv,
    float* __restrict__ Cq, float* __restrict__ Ck, float* __restrict__ Cv)
{
    extern __shared__ float sm[];
    const int bx = blockIdx.x, by = blockIdx.y;

    const float* B; float* C; int N; int bxl; bool rnd;
    if (bx < 32)      { B = Bq; C = Cq; N = QD;  bxl = bx;      rnd = false; }
    else if (bx < 40) { B = Bk; C = Ck; N = KVD; bxl = bx - 32; rnd = false; }
    else              { B = Bv; C = Cv; N = KVD; bxl = bx - 40; rnd = true;  }

    GemmMaps mp = make_maps(threadIdx.x);
    gemm_body(mp, sm,
              A + (size_t)by * BM * DIMM,
              B + (size_t)bxl * BN,
              C + (size_t)by * BM * N + (size_t)bxl * BN,
              N, DIMM, rnd);
}

// Generic single GEMM (out-projection)
__global__ __launch_bounds__(256, 2) void gemm_single(
    const float* __restrict__ A, const float* __restrict__ B,
    float* __restrict__ C, int M, int N, int K)
{
    extern __shared__ float sm[];
    GemmMaps mp = make_maps(threadIdx.x);
    gemm_body(mp, sm,
              A + (size_t)blockIdx.y * BM * K,
              B + (size_t)blockIdx.x * BN,
              C + (size_t)blockIdx.y * BM * N + (size_t)blockIdx.x * BN,
              N, K, false);
}

// ---------------------------------------------------------------------------
// RoPE (interleaved pairs); RND pre-rounds output to tf32 bits (for K)
// ---------------------------------------------------------------------------
template<bool RND>
__global__ void rope_kernel(float* __restrict__ t,
                            const float* __restrict__ fc,
                            const float* __restrict__ fs,
                            int nheads, int total)
{
    int idx = blockIdx.x * blockDim.x + threadIdx.x;
    if (idx >= total) return;
    int p = idx & 63;
    int h = (idx >> 6) % nheads;
    int s = idx / (64 * nheads);
    float c  = fc[s * 64 + p];
    float sn = fs[s * 64 + p];
    float* base = t + (size_t)s * nheads * HD + h * HD + 2 * p;
    float re = base[0], im = base[1];
    float o0 = re * c - im * sn;
    float o1 = re * sn + im * c;
    if (RND) {
        o0 = __uint_as_float(f2tf32(o0));
        o1 = __uint_as_float(f2tf32(o1));
    }
    base[0] = o0;
    base[1] = o1;
}

// ===========================================================================
// Tensor-core flash attention v4 (unchanged from R13)
// ===========================================================================
#define QSTR 132
#define VSTR 136
#define SSTR 68
#define FA_Q_FLOATS   (64 * QSTR)
#define FA_KV_FLOATS  (64 * VSTR)
#define FA_S_FLOATS   (64 * SSTR)
#define FA_SMEM_FLOATS (FA_Q_FLOATS + FA_KV_FLOATS + FA_S_FLOATS + 192)
#define FA_SMEM_BYTES  (FA_SMEM_FLOATS * 4)   // 86784

__global__ __launch_bounds__(256, 2) void flash_attn_tc(
    const float* __restrict__ Q, const float* __restrict__ K,
    const float* __restrict__ V, float* __restrict__ O)
{
    extern __shared__ float sm[];
    float* Qt   = sm;
    float* KVs  = sm + FA_Q_FLOATS;
    float* Ss   = KVs + FA_KV_FLOATS;
    float* mrow = Ss + FA_S_FLOATS;
    float* lrow = mrow + 64;
    float* arow = lrow + 64;

    const int tid  = threadIdx.x;
    const int qb   = blockIdx.x, h = blockIdx.y, kvh = h >> 2;
    const int lane = tid & 31;
    const int warp = tid >> 5;
    const int g    = lane >> 2;
    const int tg   = lane & 3;
    const int mi   = warp & 3;
    const int nj   = warp >> 2;
    const int lr   = tid >> 5;
    const int ld4  = (tid & 31) << 2;
    const float scale = 0.08838834764831845f;

    const int mrow0 = mi * 16 + g;
    const int sr = tid >> 2;
    const int sq = (tid & 3) << 4;

#pragma unroll
    for (int rr = 0; rr < 64; rr += 8) {
        float4 v = *(const float4*)(Q + (size_t)(qb * 64 + lr + rr) * QD + h * HD + ld4);
        float4 w;
        w.x = __uint_as_float(f2tf32(v.x * scale));
        w.y = __uint_as_float(f2tf32(v.y * scale));
        w.z = __uint_as_float(f2tf32(v.z * scale));
        w.w = __uint_as_float(f2tf32(v.w * scale));
        *(float4*)(Qt + (lr + rr) * QSTR + ld4) = w;
    }
    if (tid < 64) { mrow[tid] = -1e30f; lrow[tid] = 0.f; }

    float accO[8][4];
#pragma unroll
    for (int ns = 0; ns < 8; ns++)
#pragma unroll
        for (int r = 0; r < 4; r++) accO[ns][r] = 0.f;

#pragma unroll
    for (int rr = 0; rr < 64; rr += 8)
        cp_async16(KVs + (lr + rr) * QSTR + ld4,
                   K + (size_t)(lr + rr) * KVD + kvh * HD + ld4);
    cp_commit();
    cp_wait0();
    __syncthreads();

    for (int kb = 0; kb <= qb; kb++) {
        float cS[4][4];
#pragma unroll
        for (int ns = 0; ns < 4; ns++)
#pragma unroll
            for (int r = 0; r < 4; r++) cS[ns][r] = 0.f;

#pragma unroll
        for (int k8 = 0; k8 < HD; k8 += 8) {
            uint32_t a[4];
            a[0] = __float_as_uint(Qt[(mrow0)     * QSTR + k8 + tg]);
            a[1] = __float_as_uint(Qt[(mrow0 + 8) * QSTR + k8 + tg]);
            a[2] = __float_as_uint(Qt[(mrow0)     * QSTR + k8 + tg + 4]);
            a[3] = __float_as_uint(Qt[(mrow0 + 8) * QSTR + k8 + tg + 4]);
#pragma unroll
            for (int ns = 0; ns < 4; ns++) {
                const int c = nj * 32 + ns * 8 + g;
                uint32_t b[2];
                b[0] = __float_as_uint(KVs[c * QSTR + k8 + tg]);
                b[1] = __float_as_uint(KVs[c * QSTR + k8 + tg + 4]);
                mma_tf32(cS[ns], a, b);
            }
        }
#pragma unroll
        for (int ns = 0; ns < 4; ns++) {
            const int cc = nj * 32 + ns * 8 + 2 * tg;
            *(float2*)(Ss + (mrow0)     * SSTR + cc) = make_float2(cS[ns][0], cS[ns][1]);
            *(float2*)(Ss + (mrow0 + 8) * SSTR + cc) = make_float2(cS[ns][2], cS[ns][3]);
        }
        __syncthreads();

#pragma unroll
        for (int rr = 0; rr < 64; rr += 8)
            cp_async16(KVs + (lr + rr) * VSTR + ld4,
                       V + (size_t)(kb * 64 + lr + rr) * KVD + kvh * HD + ld4);
        cp_commit();

        {
            const int lim = (kb == qb) ? (sr + 1) : 64;
            float* srow = Ss + sr * SSTR + sq;
            float4 s0 = *(float4*)(srow);
            float4 s1 = *(float4*)(srow + 4);
            float4 s2 = *(float4*)(srow + 8);
            float4 s3 = *(float4*)(srow + 12);
            float sv[16] = {s0.x,s0.y,s0.z,s0.w, s1.x,s1.y,s1.z,s1.w,
                            s2.x,s2.y,s2.z,s2.w, s3.x,s3.y,s3.z,s3.w};
            float mx = -1e30f;
#pragma unroll
            for (int c = 0; c < 16; c++)
                if (sq + c < lim) mx = fmaxf(mx, sv[c]);
            mx = fmaxf(mx, __shfl_xor_sync(0xffffffffu, mx, 1));
            mx = fmaxf(mx, __shfl_xor_sync(0xffffffffu, mx, 2));
            float mold = mrow[sr];
            mx = fmaxf(mx, mold);
            float sum = 0.f;
#pragma unroll
            for (int c = 0; c < 16; c++) {
                float p = (sq + c < lim) ? __expf(sv[c] - mx) : 0.f;
                p = __uint_as_float(f2tf32(p));
                sv[c] = p;
                sum += p;
            }
            sum += __shfl_xor_sync(0xffffffffu, sum, 1);
            sum += __shfl_xor_sync(0xffffffffu, sum, 2);
            *(float4*)(srow)      = make_float4(sv[0],  sv[1],  sv[2],  sv[3]);
            *(float4*)(srow + 4)  = make_float4(sv[4],  sv[5],  sv[6],  sv[7]);
            *(float4*)(srow + 8)  = make_float4(sv[8],  sv[9],  sv[10], sv[11]);
            *(float4*)(srow + 12) = make_float4(sv[12], sv[13], sv[14], sv[15]);
            if ((tid & 3) == 0) {
                float alpha = __expf(mold - mx);
                mrow[sr] = mx;
                lrow[sr] = lrow[sr] * alpha + sum;
                arow[sr] = alpha;
            }
        }
        cp_wait0();
        __syncthreads();

        {
            float a0 = arow[mrow0], a1 = arow[mrow0 + 8];
#pragma unroll
            for (int ns = 0; ns < 8; ns++) {
                accO[ns][0] *= a0; accO[ns][1] *= a0;
                accO[ns][2] *= a1; accO[ns][3] *= a1;
            }
        }
#pragma unroll
        for (int k8 = 0; k8 < 64; k8 += 8) {
            uint32_t ap[4];
            ap[0] = __float_as_uint(Ss[(mrow0)     * SSTR + k8 + tg]);
            ap[1] = __float_as_uint(Ss[(mrow0 + 8) * SSTR + k8 + tg]);
            ap[2] = __float_as_uint(Ss[(mrow0)     * SSTR + k8 + tg + 4]);
            ap[3] = __float_as_uint(Ss[(mrow0 + 8) * SSTR + k8 + tg + 4]);
#pragma unroll
            for (int ns = 0; ns < 8; ns++) {
                const int c = nj * 64 + ns * 8 + g;
                uint32_t b[2];
                b[0] = __float_as_uint(KVs[(k8 + tg)     * VSTR + c]);
                b[1] = __float_as_uint(KVs[(k8 + tg + 4) * VSTR + c]);
                mma_tf32(accO[ns], ap, b);
            }
        }
        __syncthreads();

        if (kb + 1 <= qb) {
#pragma unroll
            for (int rr = 0; rr < 64; rr += 8)
                cp_async16(KVs + (lr + rr) * QSTR + ld4,
                           K + (size_t)((kb + 1) * 64 + lr + rr) * KVD + kvh * HD + ld4);
            cp_commit();
            cp_wait0();
            __syncthreads();
        }
    }

    const float inv0 = 1.f / lrow[mrow0];
    const float inv1 = 1.f / lrow[mrow0 + 8];
#pragma unroll
    for (int ns = 0; ns < 8; ns++) {
        const int cc = h * HD + nj * 64 + ns * 8 + 2 * tg;
        float* op0 = O + (size_t)(qb * 64 + mrow0) * QD + cc;
        float* op1 = O + (size_t)(qb * 64 + mrow0 + 8) * QD + cc;
        *(float2*)op0 = make_float2(__uint_as_float(f2tf32(accO[ns][0] * inv0)),
                                    __uint_as_float(f2tf32(accO[ns][1] * inv0)));
        *(float2*)op1 = make_float2(__uint_as_float(f2tf32(accO[ns][2] * inv1)),
                                    __uint_as_float(f2tf32(accO[ns][3] * inv1)));
    }
}

// ---------------------------------------------------------------------------
// Launch
// ---------------------------------------------------------------------------
extern "C" void kernel_launch(void* const* d_in, const int* in_sizes, int n_in,
                              void* d_out, int out_size)
{
    (void)in_sizes; (void)n_in; (void)out_size;
    const float* x  = (const float*)d_in[0];
    const float* wq = (const float*)d_in[1];
    const float* wk = (const float*)d_in[2];
    const float* wv = (const float*)d_in[3];
    const float* wo = (const float*)d_in[4];
    const float* fc = (const float*)d_in[5];
    const float* fs = (const float*)d_in[6];
    float* out = (float*)d_out;

    float *q, *k, *v, *att, *pwq, *pwk, *pwv, *pwo;
    cudaGetSymbolAddress((void**)&q,   g_q);
    cudaGetSymbolAddress((void**)&k,   g_k);
    cudaGetSymbolAddress((void**)&v,   g_v);
    cudaGetSymbolAddress((void**)&att, g_att);
    cudaGetSymbolAddress((void**)&pwq, g_wq);
    cudaGetSymbolAddress((void**)&pwk, g_wk);
    cudaGetSymbolAddress((void**)&pwv, g_wv);
    cudaGetSymbolAddress((void**)&pwo, g_wo);

    cudaFuncSetAttribute(gemm_qkv,
                         cudaFuncAttributeMaxDynamicSharedMemorySize, GEMM_SMEM_BYTES);
    cudaFuncSetAttribute(gemm_single,
                         cudaFuncAttributeMaxDynamicSharedMemorySize, GEMM_SMEM_BYTES);
    cudaFuncSetAttribute(flash_attn_tc,
                         cudaFuncAttributeMaxDynamicSharedMemorySize, FA_SMEM_BYTES);

    // Pre-round activations + weights to tf32 (bit-identical to rounding at use)
    int n4x = SEQ * DIMM / 4;
    cvt_tf32_kernel<<<(n4x + 255) / 256, 256>>>(x, att, n4x);
    int n4q = DIMM * QD / 4;
    cvt_tf32_kernel<<<(n4q + 255) / 256, 256>>>(wq, pwq, n4q);
    int n4kv = DIMM * KVD / 4;
    cvt_tf32_kernel<<<(n4kv + 255) / 256, 256>>>(wk, pwk, n4kv);
    cvt_tf32_kernel<<<(n4kv + 255) / 256, 256>>>(wv, pwv, n4kv);
    int n4o = QD * DIMM / 4;
    cvt_tf32_kernel<<<(n4o + 255) / 256, 256>>>(wo, pwo, n4o);

    // Fused QKV projection (768 CTAs, 2 CTAs/SM)
    gemm_qkv<<<dim3(48, SEQ / BM), 256, GEMM_SMEM_BYTES>>>(att, pwq, pwk, pwv, q, k, v);

    // RoPE (K output pre-rounded to tf32)
    int totq = SEQ * NHEADS * (HD / 2);
    int totk = SEQ * NKVH * (HD / 2);
    rope_kernel<false><<<(totq + 255) / 256, 256>>>(q, fc, fs, NHEADS, totq);
    rope_kernel<true ><<<(totk + 255) / 256, 256>>>(k, fc, fs, NKVH, totk);

    // Fused causal attention (writes att pre-rounded)
    flash_attn_tc<<<dim3(SEQ / 64, NHEADS), 256, FA_SMEM_BYTES>>>(q, k, v, att);

    // Output projection
    gemm_single<<<dim3(DIMM / BN, SEQ / BM), 256, GEMM_SMEM_BYTES>>>(att, pwo, out, SEQ, DIMM, QD);
}